// round 16
// baseline (speedup 1.0000x reference)
#include <cuda_runtime.h>
#include <cuda_fp16.h>
#include <cstdint>
#include <math.h>

typedef unsigned int u32;

#define Bb 2
#define Ll 2048
#define Mm 2048
#define Dd 1024
#define Hh 16
#define DHh 64
#define FFf 4096
#define WINW 64
#define RB (Bb*Ll)      // 4096 rows
#define SEG (RB*Dd)     // 4194304

#define M1 (1024*1024)

// fp32 scratch: btmp, bx1, bx2
__device__ float g_f32[(size_t)SEG*3];
// fp16 scratch (76 M1 halfs)
__device__ __half g_f16[(size_t)76*M1];

#define CP16(dst, src) asm volatile("cp.async.cg.shared.global [%0], [%1], 16;" :: "r"(dst), "l"(src))
#define CPCOMMIT()     asm volatile("cp.async.commit_group;")

__device__ __forceinline__ u32 pkh2(float x, float y) {
    __half2 h = __floats2half2_rn(x, y);
    return *(u32*)&h;
}

// ---------------------------------------------------------------------------
// Batched fp32 -> fp16 conversion (weights only: 10 tensors).
// ---------------------------------------------------------------------------
struct CvtJob { const float* src; __half* dst; int n; };
struct CvtArgs { CvtJob job[10]; };

__global__ __launch_bounds__(256) void cvt_kernel(CvtArgs a) {
    CvtJob j = a.job[blockIdx.y];
    int stride = gridDim.x * 256 * 8;
    for (int base = (blockIdx.x * 256 + threadIdx.x) * 8; base < j.n; base += stride) {
        float4 f0 = *(const float4*)(j.src + base);
        float4 f1 = *(const float4*)(j.src + base + 4);
        uint4 o;
        o.x = pkh2(f0.x, f0.y); o.y = pkh2(f0.z, f0.w);
        o.z = pkh2(f1.x, f1.y); o.w = pkh2(f1.z, f1.w);
        *(uint4*)(j.dst + base) = o;
    }
}

// ---------------------------------------------------------------------------
// Core fp16 tensor-core GEMM body (R10 best-passing version).
// 3-stage cp.async ring, 128x128x32 tile, 8 warps, operand-prefetch loop.
// ---------------------------------------------------------------------------
template<bool GELU>
__device__ __forceinline__ void hgemm_body(
    const __half* __restrict__ A, const __half* __restrict__ Wm,
    const float* __restrict__ bias, float* __restrict__ C32,
    __half* __restrict__ C16, int K, int N,
    int row0, int col0, unsigned char* smem_buf)
{
    const int tid = threadIdx.x;
    const int lane = tid & 31, wid = tid >> 5;
    const int warp_m = wid >> 2, warp_n = wid & 3;
    const u32 sbase = (u32)__cvta_generic_to_shared(smem_buf);

    float acc[4][4][4];
    #pragma unroll
    for (int i = 0; i < 4; i++)
        #pragma unroll
        for (int j = 0; j < 4; j++)
            #pragma unroll
            for (int q = 0; q < 4; q++) acc[i][j][q] = 0.f;

    const int ar = tid >> 1, akh = tid & 1;
    const int br = tid >> 3, bnh = tid & 7;

    const __half* Agp = A + (size_t)(row0 + ar) * K + akh * 16;
    const __half* Bgp = Wm + (size_t)br * N + col0 + bnh * 16;

    const u32 aDst0 = sbase + ar * 64 + (((2 * akh    ) + (ar >> 1)) & 3) * 16;
    const u32 aDst1 = sbase + ar * 64 + (((2 * akh + 1) + (ar >> 1)) & 3) * 16;
    const u32 bDst0 = sbase + 8192 + br * 256 + (((2 * bnh    ) ^ (br & 7))) * 16;
    const u32 bDst1 = sbase + 8192 + br * 256 + (((2 * bnh + 1) ^ (br & 7))) * 16;

    const int ntiles = K >> 5;

    #pragma unroll
    for (int p = 0; p < 2; p++) {
        u32 off = p * 16384;
        int k0 = p << 5;
        CP16(aDst0 + off, Agp + k0);
        CP16(aDst1 + off, Agp + k0 + 8);
        CP16(bDst0 + off, Bgp + (size_t)k0 * N);
        CP16(bDst1 + off, Bgp + (size_t)k0 * N + 8);
        CPCOMMIT();
    }

    int stage = 0, pstage = 2;
    for (int t = 0; t < ntiles; t++) {
        asm volatile("cp.async.wait_group 1;");
        __syncthreads();

        if (t + 2 < ntiles) {
            u32 off = pstage * 16384;
            int k0 = (t + 2) << 5;
            CP16(aDst0 + off, Agp + k0);
            CP16(aDst1 + off, Agp + k0 + 8);
            CP16(bDst0 + off, Bgp + (size_t)k0 * N);
            CP16(bDst1 + off, Bgp + (size_t)k0 * N + 8);
        }
        CPCOMMIT();

        const u32 sA = sbase + stage * 16384;
        const u32 sB = sA + 8192;

        #pragma unroll
        for (int ks = 0; ks < 2; ks++) {
            u32 af[4][4];
            #pragma unroll
            for (int mt = 0; mt < 4; mt++) {
                int rr = warp_m * 64 + mt * 16 + ((lane >> 3) & 1) * 8 + (lane & 7);
                int cc = ks * 2 + (lane >> 4);
                u32 aaddr = sA + rr * 64 + (((cc + (rr >> 1)) & 3) << 4);
                asm volatile(
                    "ldmatrix.sync.aligned.m8n8.x4.shared.b16 {%0,%1,%2,%3}, [%4];"
                    : "=r"(af[mt][0]), "=r"(af[mt][1]), "=r"(af[mt][2]), "=r"(af[mt][3])
                    : "r"(aaddr));
            }
            u32 bf[4][2];
            #pragma unroll
            for (int nt = 0; nt < 4; nt++) {
                int rr = ks * 16 + (lane & 15);
                int cc = warp_n * 4 + nt;
                u32 baddr = sB + rr * 256 + ((cc ^ (rr & 7)) << 4);
                asm volatile(
                    "ldmatrix.sync.aligned.m8n8.x2.trans.shared.b16 {%0,%1}, [%2];"
                    : "=r"(bf[nt][0]), "=r"(bf[nt][1]) : "r"(baddr));
            }
            #pragma unroll
            for (int nt = 0; nt < 4; nt++) {
                #pragma unroll
                for (int mt = 0; mt < 4; mt++) {
                    asm volatile(
                        "mma.sync.aligned.m16n8k16.row.col.f32.f16.f16.f32 "
                        "{%0,%1,%2,%3}, {%4,%5,%6,%7}, {%8,%9}, {%0,%1,%2,%3};"
                        : "+f"(acc[mt][nt][0]), "+f"(acc[mt][nt][1]),
                          "+f"(acc[mt][nt][2]), "+f"(acc[mt][nt][3])
                        : "r"(af[mt][0]), "r"(af[mt][1]), "r"(af[mt][2]), "r"(af[mt][3]),
                          "r"(bf[nt][0]), "r"(bf[nt][1]));
                }
            }
        }

        stage = (stage == 2) ? 0 : stage + 1;
        pstage = (pstage == 2) ? 0 : pstage + 1;
    }

    const int g = lane >> 2, tl = lane & 3;
    #pragma unroll
    for (int nt = 0; nt < 4; nt++) {
        int col = col0 + warp_n * 32 + nt * 8 + 2 * tl;
        float2 bb = *(const float2*)&bias[col];
        #pragma unroll
        for (int mt = 0; mt < 4; mt++) {
            int rlo = row0 + warp_m * 64 + mt * 16 + g;
            float2 olo, ohi;
            olo.x = acc[mt][nt][0] + bb.x;
            olo.y = acc[mt][nt][1] + bb.y;
            ohi.x = acc[mt][nt][2] + bb.x;
            ohi.y = acc[mt][nt][3] + bb.y;
            if (GELU) {
                olo.x = 0.5f * olo.x * (1.0f + erff(olo.x * 0.70710678118654752f));
                olo.y = 0.5f * olo.y * (1.0f + erff(olo.y * 0.70710678118654752f));
                ohi.x = 0.5f * ohi.x * (1.0f + erff(ohi.x * 0.70710678118654752f));
                ohi.y = 0.5f * ohi.y * (1.0f + erff(ohi.y * 0.70710678118654752f));
            }
            if (C32) {
                *(float2*)&C32[(size_t)rlo * N + col] = olo;
                *(float2*)&C32[(size_t)(rlo + 8) * N + col] = ohi;
            }
            if (C16) {
                __half2 hlo = __floats2half2_rn(olo.x, olo.y);
                __half2 hhi = __floats2half2_rn(ohi.x, ohi.y);
                *(__half2*)&C16[(size_t)rlo * N + col] = hlo;
                *(__half2*)&C16[(size_t)(rlo + 8) * N + col] = hhi;
            }
        }
    }
}

// single-GEMM wrapper (fp16 A)
template<bool GELU>
__global__ __launch_bounds__(256, 2) void hgemm16_kernel(
    const __half* __restrict__ A, const __half* __restrict__ Wm,
    const float* __restrict__ bias, float* __restrict__ C32,
    __half* __restrict__ C16, int K, int N)
{
    __shared__ __align__(16) unsigned char smem_buf[3 * 16384];
    hgemm_body<GELU>(A, Wm, bias, C32, C16, K, N,
                     blockIdx.y * 128, blockIdx.x * 128, smem_buf);
}

// ---------------------------------------------------------------------------
// Batched projections with fp32 A (inline convert): blockIdx.z = 1 of 5 jobs.
// A: LDG fp32 -> convert -> STS (staged 2 ahead); B: cp.async 3-stage ring.
// Group accounting: exactly one commit (B only) per iteration, as before.
// ---------------------------------------------------------------------------
struct GemmJobF { const float* A32; const __half* W; const float* bias; __half* C; };
struct Gemm5Args { GemmJobF job[5]; };

__global__ __launch_bounds__(256, 2) void hgemm16_b5_kernel(Gemm5Args a) {
    __shared__ __align__(16) unsigned char smem_buf[3 * 16384];
    GemmJobF j = a.job[blockIdx.z];
    const int K = Dd, N = Dd;
    const int row0 = blockIdx.y * 128, col0 = blockIdx.x * 128;

    const int tid = threadIdx.x;
    const int lane = tid & 31, wid = tid >> 5;
    const int warp_m = wid >> 2, warp_n = wid & 3;
    const u32 sbase = (u32)__cvta_generic_to_shared(smem_buf);

    float acc[4][4][4];
    #pragma unroll
    for (int i = 0; i < 4; i++)
        #pragma unroll
        for (int jj = 0; jj < 4; jj++)
            #pragma unroll
            for (int q = 0; q < 4; q++) acc[i][jj][q] = 0.f;

    const int ar = tid >> 1, akh = tid & 1;
    const int br = tid >> 3, bnh = tid & 7;

    const float*  Agp = j.A32 + (size_t)(row0 + ar) * K + akh * 16;
    const __half* Bgp = j.W + (size_t)br * N + col0 + bnh * 16;

    const u32 aDst0 = sbase + ar * 64 + (((2 * akh    ) + (ar >> 1)) & 3) * 16;
    const u32 aDst1 = sbase + ar * 64 + (((2 * akh + 1) + (ar >> 1)) & 3) * 16;
    const u32 bDst0 = sbase + 8192 + br * 256 + (((2 * bnh    ) ^ (br & 7))) * 16;
    const u32 bDst1 = sbase + 8192 + br * 256 + (((2 * bnh + 1) ^ (br & 7))) * 16;

    const int ntiles = K >> 5;   // 32

    // prologue: A tiles 0,1 via LDG+convert+STS; B tiles 0,1 via cp.async
    #pragma unroll
    for (int p = 0; p < 2; p++) {
        u32 off = p * 16384;
        int k0 = p << 5;
        float4 f0 = *(const float4*)(Agp + k0);
        float4 f1 = *(const float4*)(Agp + k0 + 4);
        float4 f2 = *(const float4*)(Agp + k0 + 8);
        float4 f3 = *(const float4*)(Agp + k0 + 12);
        asm volatile("st.shared.v4.b32 [%0], {%1,%2,%3,%4};" ::
            "r"(aDst0 + off), "r"(pkh2(f0.x, f0.y)), "r"(pkh2(f0.z, f0.w)),
            "r"(pkh2(f1.x, f1.y)), "r"(pkh2(f1.z, f1.w)));
        asm volatile("st.shared.v4.b32 [%0], {%1,%2,%3,%4};" ::
            "r"(aDst1 + off), "r"(pkh2(f2.x, f2.y)), "r"(pkh2(f2.z, f2.w)),
            "r"(pkh2(f3.x, f3.y)), "r"(pkh2(f3.z, f3.w)));
        CP16(bDst0 + off, Bgp + (size_t)k0 * N);
        CP16(bDst1 + off, Bgp + (size_t)k0 * N + 8);
        CPCOMMIT();
    }

    int stage = 0, pstage = 2;
    for (int t = 0; t < ntiles; t++) {
        // issue A(t+2) global loads early (gmem read only; no smem hazard)
        float4 f0, f1, f2, f3;
        bool havA = (t + 2 < ntiles);
        if (havA) {
            int k0 = (t + 2) << 5;
            f0 = *(const float4*)(Agp + k0);
            f1 = *(const float4*)(Agp + k0 + 4);
            f2 = *(const float4*)(Agp + k0 + 8);
            f3 = *(const float4*)(Agp + k0 + 12);
        }

        asm volatile("cp.async.wait_group 1;");
        __syncthreads();

        if (havA) {
            u32 off = pstage * 16384;
            int k0 = (t + 2) << 5;
            asm volatile("st.shared.v4.b32 [%0], {%1,%2,%3,%4};" ::
                "r"(aDst0 + off), "r"(pkh2(f0.x, f0.y)), "r"(pkh2(f0.z, f0.w)),
                "r"(pkh2(f1.x, f1.y)), "r"(pkh2(f1.z, f1.w)));
            asm volatile("st.shared.v4.b32 [%0], {%1,%2,%3,%4};" ::
                "r"(aDst1 + off), "r"(pkh2(f2.x, f2.y)), "r"(pkh2(f2.z, f2.w)),
                "r"(pkh2(f3.x, f3.y)), "r"(pkh2(f3.z, f3.w)));
            CP16(bDst0 + off, Bgp + (size_t)k0 * N);
            CP16(bDst1 + off, Bgp + (size_t)k0 * N + 8);
        }
        CPCOMMIT();

        const u32 sA = sbase + stage * 16384;
        const u32 sB = sA + 8192;

        #pragma unroll
        for (int ks = 0; ks < 2; ks++) {
            u32 af[4][4];
            #pragma unroll
            for (int mt = 0; mt < 4; mt++) {
                int rr = warp_m * 64 + mt * 16 + ((lane >> 3) & 1) * 8 + (lane & 7);
                int cc = ks * 2 + (lane >> 4);
                u32 aaddr = sA + rr * 64 + (((cc + (rr >> 1)) & 3) << 4);
                asm volatile(
                    "ldmatrix.sync.aligned.m8n8.x4.shared.b16 {%0,%1,%2,%3}, [%4];"
                    : "=r"(af[mt][0]), "=r"(af[mt][1]), "=r"(af[mt][2]), "=r"(af[mt][3])
                    : "r"(aaddr));
            }
            u32 bf[4][2];
            #pragma unroll
            for (int nt = 0; nt < 4; nt++) {
                int rr = ks * 16 + (lane & 15);
                int cc = warp_n * 4 + nt;
                u32 baddr = sB + rr * 256 + ((cc ^ (rr & 7)) << 4);
                asm volatile(
                    "ldmatrix.sync.aligned.m8n8.x2.trans.shared.b16 {%0,%1}, [%2];"
                    : "=r"(bf[nt][0]), "=r"(bf[nt][1]) : "r"(baddr));
            }
            #pragma unroll
            for (int nt = 0; nt < 4; nt++) {
                #pragma unroll
                for (int mt = 0; mt < 4; mt++) {
                    asm volatile(
                        "mma.sync.aligned.m16n8k16.row.col.f32.f16.f16.f32 "
                        "{%0,%1,%2,%3}, {%4,%5,%6,%7}, {%8,%9}, {%0,%1,%2,%3};"
                        : "+f"(acc[mt][nt][0]), "+f"(acc[mt][nt][1]),
                          "+f"(acc[mt][nt][2]), "+f"(acc[mt][nt][3])
                        : "r"(af[mt][0]), "r"(af[mt][1]), "r"(af[mt][2]), "r"(af[mt][3]),
                          "r"(bf[nt][0]), "r"(bf[nt][1]));
                }
            }
        }

        stage = (stage == 2) ? 0 : stage + 1;
        pstage = (pstage == 2) ? 0 : pstage + 1;
    }

    const int g = lane >> 2, tl = lane & 3;
    #pragma unroll
    for (int nt = 0; nt < 4; nt++) {
        int col = col0 + warp_n * 32 + nt * 8 + 2 * tl;
        float2 bb = *(const float2*)&j.bias[col];
        #pragma unroll
        for (int mt = 0; mt < 4; mt++) {
            int rlo = row0 + warp_m * 64 + mt * 16 + g;
            __half2 hlo = __floats2half2_rn(acc[mt][nt][0] + bb.x, acc[mt][nt][1] + bb.y);
            __half2 hhi = __floats2half2_rn(acc[mt][nt][2] + bb.x, acc[mt][nt][3] + bb.y);
            *(__half2*)&j.C[(size_t)rlo * N + col] = hlo;
            *(__half2*)&j.C[(size_t)(rlo + 8) * N + col] = hhi;
        }
    }
}

// ---------------------------------------------------------------------------
// MMA flash attention (unchanged — passing since R5).
// ---------------------------------------------------------------------------
template<bool WINDOWED>
__global__ __launch_bounds__(128) void attn_mma_kernel(
    const __half* __restrict__ q, const __half* __restrict__ k,
    const __half* __restrict__ v, __half* __restrict__ out, int Lk)
{
    __shared__ __align__(16) __half Q_s[64 * 64];
    __shared__ __align__(16) __half K_s[2][64 * 64];
    __shared__ __align__(16) __half V_s[2][64 * 64];

    const int tid = threadIdx.x;
    const int lane = tid & 31, wid = tid >> 5;
    const int b = blockIdx.y >> 4, h = blockIdx.y & 15;
    const int q0 = blockIdx.x * 64;

    const __half* qb = q + (size_t)(b * Ll + q0) * Dd + h * DHh;
    const __half* kb = k + (size_t)b * Lk * Dd + h * DHh;
    const __half* vb = v + (size_t)b * Lk * Dd + h * DHh;

    const u32 sQ  = (u32)__cvta_generic_to_shared(Q_s);
    const u32 sK0 = (u32)__cvta_generic_to_shared(K_s);
    const u32 sV0 = (u32)__cvta_generic_to_shared(V_s);

    const float slope = WINDOWED ? exp2f(-0.5f * (float)(h + 1)) : 0.0f;

    int t0 = 0, t1 = Lk / 64 - 1;
    if (WINDOWED) { t0 = (q0 >> 6) - 1; if (t0 < 0) t0 = 0; t1 = q0 >> 6; }

    const int lr = tid >> 1, lc0 = (tid & 1) * 4;

    #pragma unroll
    for (int c = 0; c < 4; c++) {
        int cc = lc0 + c;
        CP16(sQ + lr * 128 + ((cc ^ (lr & 7)) << 4), qb + (size_t)lr * Dd + cc * 8);
    }
    CPCOMMIT();
    {
        const __half* kr = kb + (size_t)(t0 * 64 + lr) * Dd;
        const __half* vr = vb + (size_t)(t0 * 64 + lr) * Dd;
        #pragma unroll
        for (int c = 0; c < 4; c++) {
            int cc = lc0 + c;
            u32 doff = lr * 128 + ((cc ^ (lr & 7)) << 4);
            CP16(sK0 + doff, kr + cc * 8);
            CP16(sV0 + doff, vr + cc * 8);
        }
        CPCOMMIT();
    }
    asm volatile("cp.async.wait_group 0;");
    __syncthreads();

    u32 qf[4][4];
    #pragma unroll
    for (int ks = 0; ks < 4; ks++) {
        int rr = wid * 16 + ((lane >> 3) & 1) * 8 + (lane & 7);
        int cc = ks * 2 + (lane >> 4);
        u32 addr = sQ + rr * 128 + ((cc ^ (rr & 7)) << 4);
        asm volatile(
            "ldmatrix.sync.aligned.m8n8.x4.shared.b16 {%0,%1,%2,%3}, [%4];"
            : "=r"(qf[ks][0]), "=r"(qf[ks][1]), "=r"(qf[ks][2]), "=r"(qf[ks][3])
            : "r"(addr));
    }

    float m0 = -3.4e38f, m1 = -3.4e38f, l0 = 0.f, l1 = 0.f;
    float oacc[8][4];
    #pragma unroll
    for (int nt = 0; nt < 8; nt++)
        #pragma unroll
        for (int e = 0; e < 4; e++) oacc[nt][e] = 0.f;

    const int qr = lane >> 2;
    const int qc2 = (lane & 3) << 1;

    for (int t = t0; t <= t1; t++) {
        int buf = (t - t0) & 1;
        if (t < t1) {
            u32 off = (buf ^ 1) * 8192;
            const __half* kr = kb + (size_t)((t + 1) * 64 + lr) * Dd;
            const __half* vr = vb + (size_t)((t + 1) * 64 + lr) * Dd;
            #pragma unroll
            for (int c = 0; c < 4; c++) {
                int cc = lc0 + c;
                u32 doff = lr * 128 + ((cc ^ (lr & 7)) << 4);
                CP16(sK0 + off + doff, kr + cc * 8);
                CP16(sV0 + off + doff, vr + cc * 8);
            }
            CPCOMMIT();
            asm volatile("cp.async.wait_group 1;");
        } else {
            asm volatile("cp.async.wait_group 0;");
        }
        __syncthreads();

        const u32 sK = sK0 + buf * 8192;
        const u32 sV = sV0 + buf * 8192;

        float sacc[8][4];
        #pragma unroll
        for (int nt = 0; nt < 8; nt++) {
            sacc[nt][0] = sacc[nt][1] = sacc[nt][2] = sacc[nt][3] = 0.f;
            #pragma unroll
            for (int ks = 0; ks < 4; ks++) {
                int krow = nt * 8 + (lane & 7);
                int cc = ks * 2 + ((lane >> 3) & 1);
                u32 addr = sK + krow * 128 + ((cc ^ (krow & 7)) << 4);
                u32 bf0, bf1;
                asm volatile(
                    "ldmatrix.sync.aligned.m8n8.x2.shared.b16 {%0,%1}, [%2];"
                    : "=r"(bf0), "=r"(bf1) : "r"(addr));
                asm volatile(
                    "mma.sync.aligned.m16n8k16.row.col.f32.f16.f16.f32 "
                    "{%0,%1,%2,%3}, {%4,%5,%6,%7}, {%8,%9}, {%0,%1,%2,%3};"
                    : "+f"(sacc[nt][0]), "+f"(sacc[nt][1]),
                      "+f"(sacc[nt][2]), "+f"(sacc[nt][3])
                    : "r"(qf[ks][0]), "r"(qf[ks][1]), "r"(qf[ks][2]), "r"(qf[ks][3]),
                      "r"(bf0), "r"(bf1));
            }
        }

        float mt0 = -3.4e38f, mt1 = -3.4e38f;
        #pragma unroll
        for (int nt = 0; nt < 8; nt++) {
            #pragma unroll
            for (int e = 0; e < 4; e++) {
                float s = sacc[nt][e] * 0.125f;
                if (WINDOWED) {
                    int i = q0 + wid * 16 + qr + ((e >> 1) << 3);
                    int j = t * 64 + nt * 8 + qc2 + (e & 1);
                    s += slope * (float)(j - i);
                    if (j > i || (i - j) >= WINW) s = -3.4e38f;
                }
                sacc[nt][e] = s;
                if (e < 2) mt0 = fmaxf(mt0, s); else mt1 = fmaxf(mt1, s);
            }
        }
        mt0 = fmaxf(mt0, __shfl_xor_sync(0xffffffffu, mt0, 1));
        mt0 = fmaxf(mt0, __shfl_xor_sync(0xffffffffu, mt0, 2));
        mt1 = fmaxf(mt1, __shfl_xor_sync(0xffffffffu, mt1, 1));
        mt1 = fmaxf(mt1, __shfl_xor_sync(0xffffffffu, mt1, 2));

        float mn0 = fmaxf(m0, mt0), mn1 = fmaxf(m1, mt1);
        bool dead0 = mn0 < -1e37f, dead1 = mn1 < -1e37f;
        float corr0 = dead0 ? 1.f : __expf(m0 - mn0);
        float corr1 = dead1 ? 1.f : __expf(m1 - mn1);

        float ls0 = 0.f, ls1 = 0.f;
        #pragma unroll
        for (int nt = 0; nt < 8; nt++) {
            float p0 = dead0 ? 0.f : __expf(sacc[nt][0] - mn0);
            float p1 = dead0 ? 0.f : __expf(sacc[nt][1] - mn0);
            float p2 = dead1 ? 0.f : __expf(sacc[nt][2] - mn1);
            float p3 = dead1 ? 0.f : __expf(sacc[nt][3] - mn1);
            sacc[nt][0] = p0; sacc[nt][1] = p1; sacc[nt][2] = p2; sacc[nt][3] = p3;
            ls0 += p0 + p1; ls1 += p2 + p3;
        }
        ls0 += __shfl_xor_sync(0xffffffffu, ls0, 1);
        ls0 += __shfl_xor_sync(0xffffffffu, ls0, 2);
        ls1 += __shfl_xor_sync(0xffffffffu, ls1, 1);
        ls1 += __shfl_xor_sync(0xffffffffu, ls1, 2);

        l0 = l0 * corr0 + ls0;
        l1 = l1 * corr1 + ls1;
        m0 = mn0; m1 = mn1;

        #pragma unroll
        for (int nt = 0; nt < 8; nt++) {
            oacc[nt][0] *= corr0; oacc[nt][1] *= corr0;
            oacc[nt][2] *= corr1; oacc[nt][3] *= corr1;
        }

        #pragma unroll
        for (int ks = 0; ks < 4; ks++) {
            __half2 ph0 = __floats2half2_rn(sacc[2*ks][0], sacc[2*ks][1]);
            __half2 ph1 = __floats2half2_rn(sacc[2*ks][2], sacc[2*ks][3]);
            __half2 ph2 = __floats2half2_rn(sacc[2*ks+1][0], sacc[2*ks+1][1]);
            __half2 ph3 = __floats2half2_rn(sacc[2*ks+1][2], sacc[2*ks+1][3]);
            u32 pa0 = *(u32*)&ph0, pa1 = *(u32*)&ph1;
            u32 pa2 = *(u32*)&ph2, pa3 = *(u32*)&ph3;
            #pragma unroll
            for (int nt = 0; nt < 8; nt++) {
                int vrow = ks * 16 + (lane & 15);
                u32 addr = sV + vrow * 128 + ((nt ^ (vrow & 7)) << 4);
                u32 vf0, vf1;
                asm volatile(
                    "ldmatrix.sync.aligned.m8n8.x2.trans.shared.b16 {%0,%1}, [%2];"
                    : "=r"(vf0), "=r"(vf1) : "r"(addr));
                asm volatile(
                    "mma.sync.aligned.m16n8k16.row.col.f32.f16.f16.f32 "
                    "{%0,%1,%2,%3}, {%4,%5,%6,%7}, {%8,%9}, {%0,%1,%2,%3};"
                    : "+f"(oacc[nt][0]), "+f"(oacc[nt][1]),
                      "+f"(oacc[nt][2]), "+f"(oacc[nt][3])
                    : "r"(pa0), "r"(pa1), "r"(pa2), "r"(pa3),
                      "r"(vf0), "r"(vf1));
            }
        }
        __syncthreads();
    }

    float inv0 = 1.0f / l0, inv1 = 1.0f / l1;
    int row_lo = q0 + wid * 16 + qr;
    __half* ob = out + (size_t)(b * Ll) * Dd + h * DHh;
    #pragma unroll
    for (int nt = 0; nt < 8; nt++) {
        __half2 h0 = __floats2half2_rn(oacc[nt][0] * inv0, oacc[nt][1] * inv0);
        __half2 h1 = __floats2half2_rn(oacc[nt][2] * inv1, oacc[nt][3] * inv1);
        *(__half2*)(ob + (size_t)row_lo * Dd + nt * 8 + qc2) = h0;
        *(__half2*)(ob + (size_t)(row_lo + 8) * Dd + nt * 8 + qc2) = h1;
    }
}

// ---------------------------------------------------------------------------
// out = LayerNorm(a + bres) * g + be. Optional fp16 mirror.
// ---------------------------------------------------------------------------
__global__ __launch_bounds__(256) void add_ln_kernel(
    const float* __restrict__ a, const float* __restrict__ bres,
    const float* __restrict__ g, const float* __restrict__ be,
    float* __restrict__ out, __half* __restrict__ out16)
{
    const int row = blockIdx.x;
    const int tid = threadIdx.x;
    const int d4 = tid << 2;

    float4 va = *(const float4*)(a + (size_t)row * Dd + d4);
    float4 vb = *(const float4*)(bres + (size_t)row * Dd + d4);
    float x0 = va.x + vb.x, x1 = va.y + vb.y, x2 = va.z + vb.z, x3 = va.w + vb.w;

    float s = x0 + x1 + x2 + x3;
    float ss = x0 * x0 + x1 * x1 + x2 * x2 + x3 * x3;

    #pragma unroll
    for (int off = 16; off >= 1; off >>= 1) {
        s  += __shfl_down_sync(0xffffffffu, s,  off);
        ss += __shfl_down_sync(0xffffffffu, ss, off);
    }
    __shared__ float rs[8], rss[8];
    __shared__ float s_mu, s_rstd;
    if ((tid & 31) == 0) { rs[tid >> 5] = s; rss[tid >> 5] = ss; }
    __syncthreads();
    if (tid == 0) {
        float S = 0.f, SS = 0.f;
        #pragma unroll
        for (int w = 0; w < 8; w++) { S += rs[w]; SS += rss[w]; }
        float mu = S * (1.0f / Dd);
        float var = SS * (1.0f / Dd) - mu * mu;
        s_mu = mu;
        s_rstd = rsqrtf(var + 1e-5f);
    }
    __syncthreads();
    float mu = s_mu, rstd = s_rstd;

    float4 gg = *(const float4*)(g + d4);
    float4 bb = *(const float4*)(be + d4);
    float4 o;
    o.x = (x0 - mu) * rstd * gg.x + bb.x;
    o.y = (x1 - mu) * rstd * gg.y + bb.y;
    o.z = (x2 - mu) * rstd * gg.z + bb.z;
    o.w = (x3 - mu) * rstd * gg.w + bb.w;
    *(float4*)(out + (size_t)row * Dd + d4) = o;
    if (out16) {
        __half2 h0 = __floats2half2_rn(o.x, o.y);
        __half2 h1 = __floats2half2_rn(o.z, o.w);
        uint2 ho; ho.x = *(u32*)&h0; ho.y = *(u32*)&h1;
        *(uint2*)(out16 + (size_t)row * Dd + d4) = ho;
    }
}

// ---------------------------------------------------------------------------
extern "C" void kernel_launch(void* const* d_in, const int* in_sizes, int n_in,
                              void* d_out, int out_size)
{
    const float* x   = (const float*)d_in[0];
    const float* mem = (const float*)d_in[1];

    const float *swq, *sbq, *swk, *sbk, *swv, *sbv, *swo, *sbo;
    const float *cwq, *cbq, *cwk, *cbk, *cwv, *cbv, *cwo, *cbo;
    const float *w1, *b1, *w2, *b2, *g1, *be1, *g2, *be2, *g3, *be3;

    if (in_sizes[3] == Dd) {
        swq=(const float*)d_in[2];  sbq=(const float*)d_in[3];
        swk=(const float*)d_in[4];  sbk=(const float*)d_in[5];
        swv=(const float*)d_in[6];  sbv=(const float*)d_in[7];
        swo=(const float*)d_in[8];  sbo=(const float*)d_in[9];
        cwq=(const float*)d_in[10]; cbq=(const float*)d_in[11];
        cwk=(const float*)d_in[12]; cbk=(const float*)d_in[13];
        cwv=(const float*)d_in[14]; cbv=(const float*)d_in[15];
        cwo=(const float*)d_in[16]; cbo=(const float*)d_in[17];
        w1=(const float*)d_in[18];  b1=(const float*)d_in[19];
        w2=(const float*)d_in[20];  b2=(const float*)d_in[21];
        g1=(const float*)d_in[22];  be1=(const float*)d_in[23];
        g2=(const float*)d_in[24];  be2=(const float*)d_in[25];
        g3=(const float*)d_in[26];  be3=(const float*)d_in[27];
    } else {
        swq=(const float*)d_in[2];  swk=(const float*)d_in[3];
        swv=(const float*)d_in[4];  swo=(const float*)d_in[5];
        sbq=(const float*)d_in[6];  sbk=(const float*)d_in[7];
        sbv=(const float*)d_in[8];  sbo=(const float*)d_in[9];
        cwq=(const float*)d_in[10]; cwk=(const float*)d_in[11];
        cwv=(const float*)d_in[12]; cwo=(const float*)d_in[13];
        cbq=(const float*)d_in[14]; cbk=(const float*)d_in[15];
        cbv=(const float*)d_in[16]; cbo=(const float*)d_in[17];
        w1=(const float*)d_in[18];  b1=(const float*)d_in[19];
        w2=(const float*)d_in[20];  b2=(const float*)d_in[21];
        g1=(const float*)d_in[22];  g2=(const float*)d_in[23];
        g3=(const float*)d_in[24];
        be1=(const float*)d_in[25]; be2=(const float*)d_in[26];
        be3=(const float*)d_in[27];
    }

    float* s32 = nullptr;
    cudaGetSymbolAddress((void**)&s32, g_f32);
    __half* s16 = nullptr;
    cudaGetSymbolAddress((void**)&s16, g_f16);

    float* btmp = s32;
    float* bx1  = s32 + (size_t)SEG;
    float* bx2  = s32 + (size_t)SEG * 2;

    __half* wq16   = s16 + (size_t)8*M1;
    __half* wk16   = s16 + (size_t)9*M1;
    __half* wv16   = s16 + (size_t)10*M1;
    __half* wo16   = s16 + (size_t)11*M1;
    __half* cq16   = s16 + (size_t)12*M1;
    __half* ck16   = s16 + (size_t)13*M1;
    __half* cv16   = s16 + (size_t)14*M1;
    __half* co16   = s16 + (size_t)15*M1;
    __half* w1_16  = s16 + (size_t)16*M1;
    __half* w2_16  = s16 + (size_t)20*M1;
    __half* bq16   = s16 + (size_t)24*M1;
    __half* bk16   = s16 + (size_t)28*M1;
    __half* bv16   = s16 + (size_t)32*M1;
    __half* batt16 = s16 + (size_t)36*M1;
    __half* bx1_16 = s16 + (size_t)40*M1;
    __half* bx2_16 = s16 + (size_t)44*M1;
    __half* bff16  = s16 + (size_t)48*M1;
    __half* bk2    = s16 + (size_t)64*M1;   // cross K
    __half* bv2    = s16 + (size_t)68*M1;   // cross V

    CvtArgs ca;
    ca.job[0] = { swq, wq16,  M1 };
    ca.job[1] = { swk, wk16,  M1 };
    ca.job[2] = { swv, wv16,  M1 };
    ca.job[3] = { swo, wo16,  M1 };
    ca.job[4] = { cwq, cq16,  M1 };
    ca.job[5] = { cwk, ck16,  M1 };
    ca.job[6] = { cwv, cv16,  M1 };
    ca.job[7] = { cwo, co16,  M1 };
    ca.job[8] = { w1,  w1_16, 4*M1 };
    ca.job[9] = { w2,  w2_16, 4*M1 };
    dim3 gCvt(512, 10);
    cvt_kernel<<<gCvt, 256>>>(ca);

    dim3 gP(Dd / 128, RB / 128);
    dim3 gP5(Dd / 128, RB / 128, 5);
    dim3 gF1(FFf / 128, RB / 128);
    dim3 gAttn(Ll / 64, Bb * Hh);

    // ---- fused projections (fp32 activations, inline convert) ----
    Gemm5Args g5;
    g5.job[0] = { x,   wq16, sbq, bq16 };
    g5.job[1] = { x,   wk16, sbk, bk16 };
    g5.job[2] = { x,   wv16, sbv, bv16 };
    g5.job[3] = { mem, ck16, cbk, bk2  };
    g5.job[4] = { mem, cv16, cbv, bv2  };
    hgemm16_b5_kernel<<<gP5, 256>>>(g5);

    // ---- self-attention ----
    attn_mma_kernel<true><<<gAttn, 128>>>(bq16, bk16, bv16, batt16, Ll);
    hgemm16_kernel<false><<<gP, 256>>>(batt16, wo16, sbo, btmp, nullptr, Dd, Dd);
    add_ln_kernel<<<RB, 256>>>(x, btmp, g1, be1, bx1, bx1_16);

    // ---- cross-attention ----
    hgemm16_kernel<false><<<gP, 256>>>(bx1_16, cq16, cbq, nullptr, bq16, Dd, Dd);
    attn_mma_kernel<false><<<gAttn, 128>>>(bq16, bk2, bv2, batt16, Mm);
    hgemm16_kernel<false><<<gP, 256>>>(batt16, co16, cbo, btmp, nullptr, Dd, Dd);
    add_ln_kernel<<<RB, 256>>>(bx1, btmp, g2, be2, bx2, bx2_16);

    // ---- FFN ----
    hgemm16_kernel<true><<<gF1, 256>>>(bx2_16, w1_16, b1, nullptr, bff16, Dd, FFf);
    hgemm16_kernel<false><<<gP, 256>>>(bff16, w2_16, b2, btmp, nullptr, FFf, Dd);
    add_ln_kernel<<<RB, 256>>>(bx2, btmp, g3, be3, (float*)d_out, nullptr);
}

// round 17
// speedup vs baseline: 1.0374x; 1.0374x over previous
#include <cuda_runtime.h>
#include <cuda_fp16.h>
#include <cstdint>
#include <math.h>

typedef unsigned int u32;

#define Bb 2
#define Ll 2048
#define Mm 2048
#define Dd 1024
#define Hh 16
#define DHh 64
#define FFf 4096
#define WINW 64
#define RB (Bb*Ll)      // 4096 rows
#define SEG (RB*Dd)     // 4194304

#define M1 (1024*1024)

// fp32 scratch: btmp, bx1, bx2
__device__ float g_f32[(size_t)SEG*3];
// fp16 scratch (76 M1 halfs)
__device__ __half g_f16[(size_t)76*M1];

#define CP16(dst, src) asm volatile("cp.async.cg.shared.global [%0], [%1], 16;" :: "r"(dst), "l"(src))
#define CPCOMMIT()     asm volatile("cp.async.commit_group;")

__device__ __forceinline__ u32 pkh2(float x, float y) {
    __half2 h = __floats2half2_rn(x, y);
    return *(u32*)&h;
}

// ---------------------------------------------------------------------------
// Batched fp32 -> fp16 conversion (pre-pass: 7 tensors).
// ---------------------------------------------------------------------------
struct CvtJob { const float* src; __half* dst; int n; };
struct CvtArgs { CvtJob job[7]; };

__global__ __launch_bounds__(256) void cvt_kernel(CvtArgs a) {
    CvtJob j = a.job[blockIdx.y];
    int stride = gridDim.x * 256 * 8;
    for (int base = (blockIdx.x * 256 + threadIdx.x) * 8; base < j.n; base += stride) {
        float4 f0 = *(const float4*)(j.src + base);
        float4 f1 = *(const float4*)(j.src + base + 4);
        uint4 o;
        o.x = pkh2(f0.x, f0.y); o.y = pkh2(f0.z, f0.w);
        o.z = pkh2(f1.x, f1.y); o.w = pkh2(f1.z, f1.w);
        *(uint4*)(j.dst + base) = o;
    }
}

// ---------------------------------------------------------------------------
// Core fp16 tensor-core GEMM body (R10 best-passing version).
// 3-stage cp.async ring, 128x128x32 tile, 8 warps, operand-prefetch loop.
// ---------------------------------------------------------------------------
template<bool GELU>
__device__ __forceinline__ void hgemm_body(
    const __half* __restrict__ A, const __half* __restrict__ Wm,
    const float* __restrict__ bias, float* __restrict__ C32,
    __half* __restrict__ C16, int K, int N,
    int row0, int col0, unsigned char* smem_buf)
{
    const int tid = threadIdx.x;
    const int lane = tid & 31, wid = tid >> 5;
    const int warp_m = wid >> 2, warp_n = wid & 3;
    const u32 sbase = (u32)__cvta_generic_to_shared(smem_buf);

    float acc[4][4][4];
    #pragma unroll
    for (int i = 0; i < 4; i++)
        #pragma unroll
        for (int j = 0; j < 4; j++)
            #pragma unroll
            for (int q = 0; q < 4; q++) acc[i][j][q] = 0.f;

    const int ar = tid >> 1, akh = tid & 1;
    const int br = tid >> 3, bnh = tid & 7;

    const __half* Agp = A + (size_t)(row0 + ar) * K + akh * 16;
    const __half* Bgp = Wm + (size_t)br * N + col0 + bnh * 16;

    const u32 aDst0 = sbase + ar * 64 + (((2 * akh    ) + (ar >> 1)) & 3) * 16;
    const u32 aDst1 = sbase + ar * 64 + (((2 * akh + 1) + (ar >> 1)) & 3) * 16;
    const u32 bDst0 = sbase + 8192 + br * 256 + (((2 * bnh    ) ^ (br & 7))) * 16;
    const u32 bDst1 = sbase + 8192 + br * 256 + (((2 * bnh + 1) ^ (br & 7))) * 16;

    const int ntiles = K >> 5;

    #pragma unroll
    for (int p = 0; p < 2; p++) {
        u32 off = p * 16384;
        int k0 = p << 5;
        CP16(aDst0 + off, Agp + k0);
        CP16(aDst1 + off, Agp + k0 + 8);
        CP16(bDst0 + off, Bgp + (size_t)k0 * N);
        CP16(bDst1 + off, Bgp + (size_t)k0 * N + 8);
        CPCOMMIT();
    }

    int stage = 0, pstage = 2;
    for (int t = 0; t < ntiles; t++) {
        asm volatile("cp.async.wait_group 1;");
        __syncthreads();

        if (t + 2 < ntiles) {
            u32 off = pstage * 16384;
            int k0 = (t + 2) << 5;
            CP16(aDst0 + off, Agp + k0);
            CP16(aDst1 + off, Agp + k0 + 8);
            CP16(bDst0 + off, Bgp + (size_t)k0 * N);
            CP16(bDst1 + off, Bgp + (size_t)k0 * N + 8);
        }
        CPCOMMIT();

        const u32 sA = sbase + stage * 16384;
        const u32 sB = sA + 8192;

        #pragma unroll
        for (int ks = 0; ks < 2; ks++) {
            u32 af[4][4];
            #pragma unroll
            for (int mt = 0; mt < 4; mt++) {
                int rr = warp_m * 64 + mt * 16 + ((lane >> 3) & 1) * 8 + (lane & 7);
                int cc = ks * 2 + (lane >> 4);
                u32 aaddr = sA + rr * 64 + (((cc + (rr >> 1)) & 3) << 4);
                asm volatile(
                    "ldmatrix.sync.aligned.m8n8.x4.shared.b16 {%0,%1,%2,%3}, [%4];"
                    : "=r"(af[mt][0]), "=r"(af[mt][1]), "=r"(af[mt][2]), "=r"(af[mt][3])
                    : "r"(aaddr));
            }
            u32 bf[4][2];
            #pragma unroll
            for (int nt = 0; nt < 4; nt++) {
                int rr = ks * 16 + (lane & 15);
                int cc = warp_n * 4 + nt;
                u32 baddr = sB + rr * 256 + ((cc ^ (rr & 7)) << 4);
                asm volatile(
                    "ldmatrix.sync.aligned.m8n8.x2.trans.shared.b16 {%0,%1}, [%2];"
                    : "=r"(bf[nt][0]), "=r"(bf[nt][1]) : "r"(baddr));
            }
            #pragma unroll
            for (int nt = 0; nt < 4; nt++) {
                #pragma unroll
                for (int mt = 0; mt < 4; mt++) {
                    asm volatile(
                        "mma.sync.aligned.m16n8k16.row.col.f32.f16.f16.f32 "
                        "{%0,%1,%2,%3}, {%4,%5,%6,%7}, {%8,%9}, {%0,%1,%2,%3};"
                        : "+f"(acc[mt][nt][0]), "+f"(acc[mt][nt][1]),
                          "+f"(acc[mt][nt][2]), "+f"(acc[mt][nt][3])
                        : "r"(af[mt][0]), "r"(af[mt][1]), "r"(af[mt][2]), "r"(af[mt][3]),
                          "r"(bf[nt][0]), "r"(bf[nt][1]));
                }
            }
        }

        stage = (stage == 2) ? 0 : stage + 1;
        pstage = (pstage == 2) ? 0 : pstage + 1;
    }

    const int g = lane >> 2, tl = lane & 3;
    #pragma unroll
    for (int nt = 0; nt < 4; nt++) {
        int col = col0 + warp_n * 32 + nt * 8 + 2 * tl;
        float2 bb = *(const float2*)&bias[col];
        #pragma unroll
        for (int mt = 0; mt < 4; mt++) {
            int rlo = row0 + warp_m * 64 + mt * 16 + g;
            float2 olo, ohi;
            olo.x = acc[mt][nt][0] + bb.x;
            olo.y = acc[mt][nt][1] + bb.y;
            ohi.x = acc[mt][nt][2] + bb.x;
            ohi.y = acc[mt][nt][3] + bb.y;
            if (GELU) {
                olo.x = 0.5f * olo.x * (1.0f + erff(olo.x * 0.70710678118654752f));
                olo.y = 0.5f * olo.y * (1.0f + erff(olo.y * 0.70710678118654752f));
                ohi.x = 0.5f * ohi.x * (1.0f + erff(ohi.x * 0.70710678118654752f));
                ohi.y = 0.5f * ohi.y * (1.0f + erff(ohi.y * 0.70710678118654752f));
            }
            if (C32) {
                *(float2*)&C32[(size_t)rlo * N + col] = olo;
                *(float2*)&C32[(size_t)(rlo + 8) * N + col] = ohi;
            }
            if (C16) {
                __half2 hlo = __floats2half2_rn(olo.x, olo.y);
                __half2 hhi = __floats2half2_rn(ohi.x, ohi.y);
                *(__half2*)&C16[(size_t)rlo * N + col] = hlo;
                *(__half2*)&C16[(size_t)(rlo + 8) * N + col] = hhi;
            }
        }
    }
}

// single-GEMM wrapper (fp16 A)
template<bool GELU>
__global__ __launch_bounds__(256, 2) void hgemm16_kernel(
    const __half* __restrict__ A, const __half* __restrict__ Wm,
    const float* __restrict__ bias, float* __restrict__ C32,
    __half* __restrict__ C16, int K, int N)
{
    __shared__ __align__(16) unsigned char smem_buf[3 * 16384];
    hgemm_body<GELU>(A, Wm, bias, C32, C16, K, N,
                     blockIdx.y * 128, blockIdx.x * 128, smem_buf);
}

// batched wrapper: z<5 -> one of 5 DxD GEMMs (R15-exact fp16-A path);
// z in 5..9 -> grid-strided fp32->fp16 conversion (weights needed later),
// overlapped with the GEMM CTAs in the same launch.
struct GemmJob { const __half* A; const __half* W; const float* bias; __half* C; };
struct Gemm5Args { GemmJob job[5]; CvtJob cvt[5]; };

__global__ __launch_bounds__(256, 2) void hgemm16_b5_kernel(Gemm5Args a) {
    __shared__ __align__(16) unsigned char smem_buf[3 * 16384];
    if (blockIdx.z < 5) {
        GemmJob j = a.job[blockIdx.z];
        hgemm_body<false>(j.A, j.W, j.bias, nullptr, j.C, Dd, Dd,
                          blockIdx.y * 128, blockIdx.x * 128, smem_buf);
    } else {
        CvtJob j = a.cvt[blockIdx.z - 5];
        int bid = blockIdx.y * gridDim.x + blockIdx.x;        // 0..255
        int nblk = gridDim.x * gridDim.y;                     // 256
        int stride = nblk * 256 * 8;
        for (int base = (bid * 256 + threadIdx.x) * 8; base < j.n; base += stride) {
            float4 f0 = *(const float4*)(j.src + base);
            float4 f1 = *(const float4*)(j.src + base + 4);
            uint4 o;
            o.x = pkh2(f0.x, f0.y); o.y = pkh2(f0.z, f0.w);
            o.z = pkh2(f1.x, f1.y); o.w = pkh2(f1.z, f1.w);
            *(uint4*)(j.dst + base) = o;
        }
    }
}

// ---------------------------------------------------------------------------
// MMA flash attention (unchanged — passing since R5).
// ---------------------------------------------------------------------------
template<bool WINDOWED>
__global__ __launch_bounds__(128) void attn_mma_kernel(
    const __half* __restrict__ q, const __half* __restrict__ k,
    const __half* __restrict__ v, __half* __restrict__ out, int Lk)
{
    __shared__ __align__(16) __half Q_s[64 * 64];
    __shared__ __align__(16) __half K_s[2][64 * 64];
    __shared__ __align__(16) __half V_s[2][64 * 64];

    const int tid = threadIdx.x;
    const int lane = tid & 31, wid = tid >> 5;
    const int b = blockIdx.y >> 4, h = blockIdx.y & 15;
    const int q0 = blockIdx.x * 64;

    const __half* qb = q + (size_t)(b * Ll + q0) * Dd + h * DHh;
    const __half* kb = k + (size_t)b * Lk * Dd + h * DHh;
    const __half* vb = v + (size_t)b * Lk * Dd + h * DHh;

    const u32 sQ  = (u32)__cvta_generic_to_shared(Q_s);
    const u32 sK0 = (u32)__cvta_generic_to_shared(K_s);
    const u32 sV0 = (u32)__cvta_generic_to_shared(V_s);

    const float slope = WINDOWED ? exp2f(-0.5f * (float)(h + 1)) : 0.0f;

    int t0 = 0, t1 = Lk / 64 - 1;
    if (WINDOWED) { t0 = (q0 >> 6) - 1; if (t0 < 0) t0 = 0; t1 = q0 >> 6; }

    const int lr = tid >> 1, lc0 = (tid & 1) * 4;

    #pragma unroll
    for (int c = 0; c < 4; c++) {
        int cc = lc0 + c;
        CP16(sQ + lr * 128 + ((cc ^ (lr & 7)) << 4), qb + (size_t)lr * Dd + cc * 8);
    }
    CPCOMMIT();
    {
        const __half* kr = kb + (size_t)(t0 * 64 + lr) * Dd;
        const __half* vr = vb + (size_t)(t0 * 64 + lr) * Dd;
        #pragma unroll
        for (int c = 0; c < 4; c++) {
            int cc = lc0 + c;
            u32 doff = lr * 128 + ((cc ^ (lr & 7)) << 4);
            CP16(sK0 + doff, kr + cc * 8);
            CP16(sV0 + doff, vr + cc * 8);
        }
        CPCOMMIT();
    }
    asm volatile("cp.async.wait_group 0;");
    __syncthreads();

    u32 qf[4][4];
    #pragma unroll
    for (int ks = 0; ks < 4; ks++) {
        int rr = wid * 16 + ((lane >> 3) & 1) * 8 + (lane & 7);
        int cc = ks * 2 + (lane >> 4);
        u32 addr = sQ + rr * 128 + ((cc ^ (rr & 7)) << 4);
        asm volatile(
            "ldmatrix.sync.aligned.m8n8.x4.shared.b16 {%0,%1,%2,%3}, [%4];"
            : "=r"(qf[ks][0]), "=r"(qf[ks][1]), "=r"(qf[ks][2]), "=r"(qf[ks][3])
            : "r"(addr));
    }

    float m0 = -3.4e38f, m1 = -3.4e38f, l0 = 0.f, l1 = 0.f;
    float oacc[8][4];
    #pragma unroll
    for (int nt = 0; nt < 8; nt++)
        #pragma unroll
        for (int e = 0; e < 4; e++) oacc[nt][e] = 0.f;

    const int qr = lane >> 2;
    const int qc2 = (lane & 3) << 1;

    for (int t = t0; t <= t1; t++) {
        int buf = (t - t0) & 1;
        if (t < t1) {
            u32 off = (buf ^ 1) * 8192;
            const __half* kr = kb + (size_t)((t + 1) * 64 + lr) * Dd;
            const __half* vr = vb + (size_t)((t + 1) * 64 + lr) * Dd;
            #pragma unroll
            for (int c = 0; c < 4; c++) {
                int cc = lc0 + c;
                u32 doff = lr * 128 + ((cc ^ (lr & 7)) << 4);
                CP16(sK0 + off + doff, kr + cc * 8);
                CP16(sV0 + off + doff, vr + cc * 8);
            }
            CPCOMMIT();
            asm volatile("cp.async.wait_group 1;");
        } else {
            asm volatile("cp.async.wait_group 0;");
        }
        __syncthreads();

        const u32 sK = sK0 + buf * 8192;
        const u32 sV = sV0 + buf * 8192;

        float sacc[8][4];
        #pragma unroll
        for (int nt = 0; nt < 8; nt++) {
            sacc[nt][0] = sacc[nt][1] = sacc[nt][2] = sacc[nt][3] = 0.f;
            #pragma unroll
            for (int ks = 0; ks < 4; ks++) {
                int krow = nt * 8 + (lane & 7);
                int cc = ks * 2 + ((lane >> 3) & 1);
                u32 addr = sK + krow * 128 + ((cc ^ (krow & 7)) << 4);
                u32 bf0, bf1;
                asm volatile(
                    "ldmatrix.sync.aligned.m8n8.x2.shared.b16 {%0,%1}, [%2];"
                    : "=r"(bf0), "=r"(bf1) : "r"(addr));
                asm volatile(
                    "mma.sync.aligned.m16n8k16.row.col.f32.f16.f16.f32 "
                    "{%0,%1,%2,%3}, {%4,%5,%6,%7}, {%8,%9}, {%0,%1,%2,%3};"
                    : "+f"(sacc[nt][0]), "+f"(sacc[nt][1]),
                      "+f"(sacc[nt][2]), "+f"(sacc[nt][3])
                    : "r"(qf[ks][0]), "r"(qf[ks][1]), "r"(qf[ks][2]), "r"(qf[ks][3]),
                      "r"(bf0), "r"(bf1));
            }
        }

        float mt0 = -3.4e38f, mt1 = -3.4e38f;
        #pragma unroll
        for (int nt = 0; nt < 8; nt++) {
            #pragma unroll
            for (int e = 0; e < 4; e++) {
                float s = sacc[nt][e] * 0.125f;
                if (WINDOWED) {
                    int i = q0 + wid * 16 + qr + ((e >> 1) << 3);
                    int j = t * 64 + nt * 8 + qc2 + (e & 1);
                    s += slope * (float)(j - i);
                    if (j > i || (i - j) >= WINW) s = -3.4e38f;
                }
                sacc[nt][e] = s;
                if (e < 2) mt0 = fmaxf(mt0, s); else mt1 = fmaxf(mt1, s);
            }
        }
        mt0 = fmaxf(mt0, __shfl_xor_sync(0xffffffffu, mt0, 1));
        mt0 = fmaxf(mt0, __shfl_xor_sync(0xffffffffu, mt0, 2));
        mt1 = fmaxf(mt1, __shfl_xor_sync(0xffffffffu, mt1, 1));
        mt1 = fmaxf(mt1, __shfl_xor_sync(0xffffffffu, mt1, 2));

        float mn0 = fmaxf(m0, mt0), mn1 = fmaxf(m1, mt1);
        bool dead0 = mn0 < -1e37f, dead1 = mn1 < -1e37f;
        float corr0 = dead0 ? 1.f : __expf(m0 - mn0);
        float corr1 = dead1 ? 1.f : __expf(m1 - mn1);

        float ls0 = 0.f, ls1 = 0.f;
        #pragma unroll
        for (int nt = 0; nt < 8; nt++) {
            float p0 = dead0 ? 0.f : __expf(sacc[nt][0] - mn0);
            float p1 = dead0 ? 0.f : __expf(sacc[nt][1] - mn0);
            float p2 = dead1 ? 0.f : __expf(sacc[nt][2] - mn1);
            float p3 = dead1 ? 0.f : __expf(sacc[nt][3] - mn1);
            sacc[nt][0] = p0; sacc[nt][1] = p1; sacc[nt][2] = p2; sacc[nt][3] = p3;
            ls0 += p0 + p1; ls1 += p2 + p3;
        }
        ls0 += __shfl_xor_sync(0xffffffffu, ls0, 1);
        ls0 += __shfl_xor_sync(0xffffffffu, ls0, 2);
        ls1 += __shfl_xor_sync(0xffffffffu, ls1, 1);
        ls1 += __shfl_xor_sync(0xffffffffu, ls1, 2);

        l0 = l0 * corr0 + ls0;
        l1 = l1 * corr1 + ls1;
        m0 = mn0; m1 = mn1;

        #pragma unroll
        for (int nt = 0; nt < 8; nt++) {
            oacc[nt][0] *= corr0; oacc[nt][1] *= corr0;
            oacc[nt][2] *= corr1; oacc[nt][3] *= corr1;
        }

        #pragma unroll
        for (int ks = 0; ks < 4; ks++) {
            __half2 ph0 = __floats2half2_rn(sacc[2*ks][0], sacc[2*ks][1]);
            __half2 ph1 = __floats2half2_rn(sacc[2*ks][2], sacc[2*ks][3]);
            __half2 ph2 = __floats2half2_rn(sacc[2*ks+1][0], sacc[2*ks+1][1]);
            __half2 ph3 = __floats2half2_rn(sacc[2*ks+1][2], sacc[2*ks+1][3]);
            u32 pa0 = *(u32*)&ph0, pa1 = *(u32*)&ph1;
            u32 pa2 = *(u32*)&ph2, pa3 = *(u32*)&ph3;
            #pragma unroll
            for (int nt = 0; nt < 8; nt++) {
                int vrow = ks * 16 + (lane & 15);
                u32 addr = sV + vrow * 128 + ((nt ^ (vrow & 7)) << 4);
                u32 vf0, vf1;
                asm volatile(
                    "ldmatrix.sync.aligned.m8n8.x2.trans.shared.b16 {%0,%1}, [%2];"
                    : "=r"(vf0), "=r"(vf1) : "r"(addr));
                asm volatile(
                    "mma.sync.aligned.m16n8k16.row.col.f32.f16.f16.f32 "
                    "{%0,%1,%2,%3}, {%4,%5,%6,%7}, {%8,%9}, {%0,%1,%2,%3};"
                    : "+f"(oacc[nt][0]), "+f"(oacc[nt][1]),
                      "+f"(oacc[nt][2]), "+f"(oacc[nt][3])
                    : "r"(pa0), "r"(pa1), "r"(pa2), "r"(pa3),
                      "r"(vf0), "r"(vf1));
            }
        }
        __syncthreads();
    }

    float inv0 = 1.0f / l0, inv1 = 1.0f / l1;
    int row_lo = q0 + wid * 16 + qr;
    __half* ob = out + (size_t)(b * Ll) * Dd + h * DHh;
    #pragma unroll
    for (int nt = 0; nt < 8; nt++) {
        __half2 h0 = __floats2half2_rn(oacc[nt][0] * inv0, oacc[nt][1] * inv0);
        __half2 h1 = __floats2half2_rn(oacc[nt][2] * inv1, oacc[nt][3] * inv1);
        *(__half2*)(ob + (size_t)row_lo * Dd + nt * 8 + qc2) = h0;
        *(__half2*)(ob + (size_t)(row_lo + 8) * Dd + nt * 8 + qc2) = h1;
    }
}

// ---------------------------------------------------------------------------
// out = LayerNorm(a + bres) * g + be. Optional fp16 mirror.
// ---------------------------------------------------------------------------
__global__ __launch_bounds__(256) void add_ln_kernel(
    const float* __restrict__ a, const float* __restrict__ bres,
    const float* __restrict__ g, const float* __restrict__ be,
    float* __restrict__ out, __half* __restrict__ out16)
{
    const int row = blockIdx.x;
    const int tid = threadIdx.x;
    const int d4 = tid << 2;

    float4 va = *(const float4*)(a + (size_t)row * Dd + d4);
    float4 vb = *(const float4*)(bres + (size_t)row * Dd + d4);
    float x0 = va.x + vb.x, x1 = va.y + vb.y, x2 = va.z + vb.z, x3 = va.w + vb.w;

    float s = x0 + x1 + x2 + x3;
    float ss = x0 * x0 + x1 * x1 + x2 * x2 + x3 * x3;

    #pragma unroll
    for (int off = 16; off >= 1; off >>= 1) {
        s  += __shfl_down_sync(0xffffffffu, s,  off);
        ss += __shfl_down_sync(0xffffffffu, ss, off);
    }
    __shared__ float rs[8], rss[8];
    __shared__ float s_mu, s_rstd;
    if ((tid & 31) == 0) { rs[tid >> 5] = s; rss[tid >> 5] = ss; }
    __syncthreads();
    if (tid == 0) {
        float S = 0.f, SS = 0.f;
        #pragma unroll
        for (int w = 0; w < 8; w++) { S += rs[w]; SS += rss[w]; }
        float mu = S * (1.0f / Dd);
        float var = SS * (1.0f / Dd) - mu * mu;
        s_mu = mu;
        s_rstd = rsqrtf(var + 1e-5f);
    }
    __syncthreads();
    float mu = s_mu, rstd = s_rstd;

    float4 gg = *(const float4*)(g + d4);
    float4 bb = *(const float4*)(be + d4);
    float4 o;
    o.x = (x0 - mu) * rstd * gg.x + bb.x;
    o.y = (x1 - mu) * rstd * gg.y + bb.y;
    o.z = (x2 - mu) * rstd * gg.z + bb.z;
    o.w = (x3 - mu) * rstd * gg.w + bb.w;
    *(float4*)(out + (size_t)row * Dd + d4) = o;
    if (out16) {
        __half2 h0 = __floats2half2_rn(o.x, o.y);
        __half2 h1 = __floats2half2_rn(o.z, o.w);
        uint2 ho; ho.x = *(u32*)&h0; ho.y = *(u32*)&h1;
        *(uint2*)(out16 + (size_t)row * Dd + d4) = ho;
    }
}

// ---------------------------------------------------------------------------
extern "C" void kernel_launch(void* const* d_in, const int* in_sizes, int n_in,
                              void* d_out, int out_size)
{
    const float* x   = (const float*)d_in[0];
    const float* mem = (const float*)d_in[1];

    const float *swq, *sbq, *swk, *sbk, *swv, *sbv, *swo, *sbo;
    const float *cwq, *cbq, *cwk, *cbk, *cwv, *cbv, *cwo, *cbo;
    const float *w1, *b1, *w2, *b2, *g1, *be1, *g2, *be2, *g3, *be3;

    if (in_sizes[3] == Dd) {
        swq=(const float*)d_in[2];  sbq=(const float*)d_in[3];
        swk=(const float*)d_in[4];  sbk=(const float*)d_in[5];
        swv=(const float*)d_in[6];  sbv=(const float*)d_in[7];
        swo=(const float*)d_in[8];  sbo=(const float*)d_in[9];
        cwq=(const float*)d_in[10]; cbq=(const float*)d_in[11];
        cwk=(const float*)d_in[12]; cbk=(const float*)d_in[13];
        cwv=(const float*)d_in[14]; cbv=(const float*)d_in[15];
        cwo=(const float*)d_in[16]; cbo=(const float*)d_in[17];
        w1=(const float*)d_in[18];  b1=(const float*)d_in[19];
        w2=(const float*)d_in[20];  b2=(const float*)d_in[21];
        g1=(const float*)d_in[22];  be1=(const float*)d_in[23];
        g2=(const float*)d_in[24];  be2=(const float*)d_in[25];
        g3=(const float*)d_in[26];  be3=(const float*)d_in[27];
    } else {
        swq=(const float*)d_in[2];  swk=(const float*)d_in[3];
        swv=(const float*)d_in[4];  swo=(const float*)d_in[5];
        sbq=(const float*)d_in[6];  sbk=(const float*)d_in[7];
        sbv=(const float*)d_in[8];  sbo=(const float*)d_in[9];
        cwq=(const float*)d_in[10]; cwk=(const float*)d_in[11];
        cwv=(const float*)d_in[12]; cwo=(const float*)d_in[13];
        cbq=(const float*)d_in[14]; cbk=(const float*)d_in[15];
        cbv=(const float*)d_in[16]; cbo=(const float*)d_in[17];
        w1=(const float*)d_in[18];  b1=(const float*)d_in[19];
        w2=(const float*)d_in[20];  b2=(const float*)d_in[21];
        g1=(const float*)d_in[22];  g2=(const float*)d_in[23];
        g3=(const float*)d_in[24];
        be1=(const float*)d_in[25]; be2=(const float*)d_in[26];
        be3=(const float*)d_in[27];
    }

    float* s32 = nullptr;
    cudaGetSymbolAddress((void**)&s32, g_f32);
    __half* s16 = nullptr;
    cudaGetSymbolAddress((void**)&s16, g_f16);

    float* btmp = s32;
    float* bx1  = s32 + (size_t)SEG;
    float* bx2  = s32 + (size_t)SEG * 2;

    __half* x16    = s16;
    __half* mem16  = s16 + (size_t)4*M1;
    __half* wq16   = s16 + (size_t)8*M1;
    __half* wk16   = s16 + (size_t)9*M1;
    __half* wv16   = s16 + (size_t)10*M1;
    __half* wo16   = s16 + (size_t)11*M1;
    __half* cq16   = s16 + (size_t)12*M1;
    __half* ck16   = s16 + (size_t)13*M1;
    __half* cv16   = s16 + (size_t)14*M1;
    __half* co16   = s16 + (size_t)15*M1;
    __half* w1_16  = s16 + (size_t)16*M1;
    __half* w2_16  = s16 + (size_t)20*M1;
    __half* bq16   = s16 + (size_t)24*M1;
    __half* bk16   = s16 + (size_t)28*M1;
    __half* bv16   = s16 + (size_t)32*M1;
    __half* batt16 = s16 + (size_t)36*M1;
    __half* bx1_16 = s16 + (size_t)40*M1;
    __half* bx2_16 = s16 + (size_t)44*M1;
    __half* bff16  = s16 + (size_t)48*M1;
    __half* bk2    = s16 + (size_t)64*M1;   // cross K
    __half* bv2    = s16 + (size_t)68*M1;   // cross V

    // pre-pass: only what the batched projections need
    CvtArgs ca;
    ca.job[0] = { x,   x16,   4*M1 };
    ca.job[1] = { mem, mem16, 4*M1 };
    ca.job[2] = { swq, wq16,  M1 };
    ca.job[3] = { swk, wk16,  M1 };
    ca.job[4] = { swv, wv16,  M1 };
    ca.job[5] = { cwk, ck16,  M1 };
    ca.job[6] = { cwv, cv16,  M1 };
    dim3 gCvt(512, 7);
    cvt_kernel<<<gCvt, 256>>>(ca);

    dim3 gP(Dd / 128, RB / 128);
    dim3 gP10(Dd / 128, RB / 128, 10);   // 5 GEMM slices + 5 cvt slices
    dim3 gF1(FFf / 128, RB / 128);
    dim3 gAttn(Ll / 64, Bb * Hh);

    // ---- fused projections + deferred weight conversions (one launch) ----
    Gemm5Args g5;
    g5.job[0] = { x16,   wq16, sbq, bq16 };
    g5.job[1] = { x16,   wk16, sbk, bk16 };
    g5.job[2] = { x16,   wv16, sbv, bv16 };
    g5.job[3] = { mem16, ck16, cbk, bk2  };
    g5.job[4] = { mem16, cv16, cbv, bv2  };
    g5.cvt[0] = { swo, wo16,  M1 };
    g5.cvt[1] = { cwq, cq16,  M1 };
    g5.cvt[2] = { cwo, co16,  M1 };
    g5.cvt[3] = { w1,  w1_16, 4*M1 };
    g5.cvt[4] = { w2,  w2_16, 4*M1 };
    hgemm16_b5_kernel<<<gP10, 256>>>(g5);

    // ---- self-attention ----
    attn_mma_kernel<true><<<gAttn, 128>>>(bq16, bk16, bv16, batt16, Ll);
    hgemm16_kernel<false><<<gP, 256>>>(batt16, wo16, sbo, btmp, nullptr, Dd, Dd);
    add_ln_kernel<<<RB, 256>>>(x, btmp, g1, be1, bx1, bx1_16);

    // ---- cross-attention ----
    hgemm16_kernel<false><<<gP, 256>>>(bx1_16, cq16, cbq, nullptr, bq16, Dd, Dd);
    attn_mma_kernel<false><<<gAttn, 128>>>(bq16, bk2, bv2, batt16, Mm);
    hgemm16_kernel<false><<<gP, 256>>>(batt16, co16, cbo, btmp, nullptr, Dd, Dd);
    add_ln_kernel<<<RB, 256>>>(bx1, btmp, g2, be2, bx2, bx2_16);

    // ---- FFN ----
    hgemm16_kernel<true><<<gF1, 256>>>(bx2_16, w1_16, b1, nullptr, bff16, Dd, FFf);
    hgemm16_kernel<false><<<gP, 256>>>(bff16, w2_16, b2, btmp, nullptr, FFf, Dd);
    add_ln_kernel<<<RB, 256>>>(bx2, btmp, g3, be3, (float*)d_out, nullptr);
}